// round 3
// baseline (speedup 1.0000x reference)
#include <cuda_runtime.h>
#include <math.h>

#define BZ   2
#define SQ   2048
#define DM   1024
#define HH   16
#define HD   64
#define MR   (BZ*SQ)      // 4096 rows total

// Scratch (device globals; no allocation allowed)
__device__ float g_q[(size_t)MR*DM];
__device__ float g_k[(size_t)MR*DM];
__device__ float g_v[(size_t)MR*DM];
__device__ float g_o[(size_t)MR*DM];

// ---------------------------------------------------------------------------
// Generic tiled FP32 GEMM: C[M,N] = A[M,K] @ B[K,N] + bias[N]
// 64x64 tile, BK=16, 256 threads, 4x4 micro-tile per thread.
// ---------------------------------------------------------------------------
__global__ __launch_bounds__(256) void gemm_kernel(
    const float* __restrict__ A, const float* __restrict__ Bm,
    const float* __restrict__ bias, float* __restrict__ C,
    int M, int N, int K)
{
    __shared__ float As[16*68];   // [kk][row], padded stride 68
    __shared__ float Bs[16*68];   // [kk][col], padded stride 68

    int tid = threadIdx.x;
    int tx = tid & 15, ty = tid >> 4;
    int m0 = blockIdx.y * 64, n0 = blockIdx.x * 64;

    float c[4][4] = {};

    for (int k0 = 0; k0 < K; k0 += 16) {
        // A tile: 64 rows x 16 cols, stored transposed As[col*68+row]
        #pragma unroll
        for (int i = 0; i < 4; i++) {
            int idx = tid + i*256;
            int col = idx & 15, row = idx >> 4;
            As[col*68 + row] = A[(size_t)(m0+row)*K + k0 + col];
        }
        // B tile: 16 rows x 64 cols, Bs[row*68+col]
        #pragma unroll
        for (int i = 0; i < 4; i++) {
            int idx = tid + i*256;
            int col = idx & 63, row = idx >> 6;
            Bs[row*68 + col] = Bm[(size_t)(k0+row)*N + n0 + col];
        }
        __syncthreads();

        #pragma unroll
        for (int kk = 0; kk < 16; kk++) {
            float4 a4 = *(const float4*)&As[kk*68 + ty*4];
            float4 b4 = *(const float4*)&Bs[kk*68 + tx*4];
            float av[4] = {a4.x, a4.y, a4.z, a4.w};
            float bv[4] = {b4.x, b4.y, b4.z, b4.w};
            #pragma unroll
            for (int i = 0; i < 4; i++)
                #pragma unroll
                for (int j = 0; j < 4; j++)
                    c[i][j] = fmaf(av[i], bv[j], c[i][j]);
        }
        __syncthreads();
    }

    #pragma unroll
    for (int i = 0; i < 4; i++) {
        int row = m0 + ty*4 + i;
        #pragma unroll
        for (int j = 0; j < 4; j++) {
            int col = n0 + tx*4 + j;
            C[(size_t)row*N + col] = c[i][j] + bias[col];
        }
    }
}

// ---------------------------------------------------------------------------
// Flash attention, static smem (<48KB). One block per (64 q-rows, head, batch).
// K-tiles of 32 rows. 256 threads.
//   S-phase: thread (tx8,ty32): tx8 = tid&7 -> score col pair base (tx8*4),
//            ty32 = tid>>3 -> q row pair base... simpler: 256 thr = 8x32 grid:
//   sx = tid&7  (8 cols of 4 -> 32 score cols), sy = tid>>3 (32 rows of 2 -> 64 q rows)
//   Each thread: 2 q-rows x 4 k-cols micro-tile for S; 2 q-rows x 4 hd-cols for O
//   (O cols: 64 hd cols -> ox = tid&15 (16x4), oy = tid>>4 (16 -> 4 rows each))
// ---------------------------------------------------------------------------
#define PST 68   // padded stride for 64-wide tiles (float4-aligned)
#define PSS 36   // padded stride for 32-wide P tile  (float4-aligned)

__global__ __launch_bounds__(256) void attn_kernel()
{
    __shared__ float Qs[64*PST];    // 64 x 64, q rows x hd (scaled)
    __shared__ float Ks[32*PST];    // 32 k-rows x 64 hd
    __shared__ float Vs[32*PST];    // 32 k-rows x 64 hd
    __shared__ float Ps[64*PSS];    // 64 q-rows x 32 k-cols (probs)
    __shared__ float mrow[64], lrow[64], arow[64];

    int tid = threadIdx.x;
    int q0 = blockIdx.x * 64;
    int h  = blockIdx.y;
    int b  = blockIdx.z;
    const float scale = 0.125f;     // 1/sqrt(64)

    // S-phase mapping: 2 q-rows x 4 score-cols per thread
    int sx = tid & 7;               // score col group: cols sx*4 .. sx*4+3
    int sy = tid >> 3;              // q row group: rows sy, sy+32
    // O-phase mapping: 4 q-rows x 4 hd-cols per thread
    int ox = tid & 15;              // hd col group: ox*4 .. ox*4+3  -> wait 16*4=64 ok
    int oy = tid >> 4;              // q rows oy, oy+16, oy+32, oy+48

    // Load Q tile (scaled): 64 rows x 16 float4
    const float* Qg = g_q + (size_t)(b*SQ + q0)*DM + h*HD;
    #pragma unroll
    for (int i = 0; i < 4; i++) {
        int idx4 = tid + i*256;
        int r = idx4 >> 4, c4 = idx4 & 15;
        float4 v = *(const float4*)(Qg + (size_t)r*DM + c4*4);
        v.x *= scale; v.y *= scale; v.z *= scale; v.w *= scale;
        *(float4*)&Qs[r*PST + c4*4] = v;
    }
    if (tid < 64) { mrow[tid] = -INFINITY; lrow[tid] = 0.f; }

    float o[4][4] = {};
    __syncthreads();

    for (int k0 = 0; k0 < SQ; k0 += 32) {
        const float* Kg = g_k + (size_t)(b*SQ + k0)*DM + h*HD;
        const float* Vg = g_v + (size_t)(b*SQ + k0)*DM + h*HD;
        // 32 rows x 16 float4 each for K and V: 512 float4's each, 256 threads
        #pragma unroll
        for (int i = 0; i < 2; i++) {
            int idx4 = tid + i*256;
            int r = idx4 >> 4, c4 = idx4 & 15;
            *(float4*)&Ks[r*PST + c4*4] = *(const float4*)(Kg + (size_t)r*DM + c4*4);
            *(float4*)&Vs[r*PST + c4*4] = *(const float4*)(Vg + (size_t)r*DM + c4*4);
        }
        __syncthreads();

        // S = Q @ K^T : 2 q-rows x 4 k-cols per thread
        float s[2][4] = {};
        #pragma unroll 16
        for (int d = 0; d < 64; d++) {
            float qv[2], kv[4];
            qv[0] = Qs[sy*PST + d];
            qv[1] = Qs[(sy+32)*PST + d];
            #pragma unroll
            for (int j = 0; j < 4; j++) kv[j] = Ks[(sx*4+j)*PST + d];
            #pragma unroll
            for (int i = 0; i < 2; i++)
                #pragma unroll
                for (int j = 0; j < 4; j++)
                    s[i][j] = fmaf(qv[i], kv[j], s[i][j]);
        }
        #pragma unroll
        for (int i = 0; i < 2; i++) {
            int q = sy + 32*i;
            *(float4*)&Ps[q*PSS + sx*4] = make_float4(s[i][0], s[i][1], s[i][2], s[i][3]);
        }
        __syncthreads();

        // Online softmax per row (first 64 threads, 1 row each; 32 cols)
        if (tid < 64) {
            int q = tid;
            float mo = mrow[q];
            float mx = mo;
            #pragma unroll 8
            for (int j = 0; j < 32; j++) mx = fmaxf(mx, Ps[q*PSS + j]);
            float sum = 0.f;
            #pragma unroll 8
            for (int j = 0; j < 32; j++) {
                float p = __expf(Ps[q*PSS + j] - mx);
                Ps[q*PSS + j] = p;
                sum += p;
            }
            float al = __expf(mo - mx);
            lrow[q] = lrow[q]*al + sum;
            mrow[q] = mx;
            arow[q] = al;
        }
        __syncthreads();

        // O += P @ V : 4 q-rows x 4 hd-cols per thread, rescale first
        float al[4];
        #pragma unroll
        for (int i = 0; i < 4; i++) al[i] = arow[oy + 16*i];
        #pragma unroll
        for (int i = 0; i < 4; i++)
            #pragma unroll
            for (int j = 0; j < 4; j++)
                o[i][j] *= al[i];

        #pragma unroll 8
        for (int kk = 0; kk < 32; kk++) {
            float pv[4], vv[4];
            #pragma unroll
            for (int i = 0; i < 4; i++) pv[i] = Ps[(oy + 16*i)*PSS + kk];
            #pragma unroll
            for (int j = 0; j < 4; j++) vv[j] = Vs[kk*PST + ox*4 + j];
            #pragma unroll
            for (int i = 0; i < 4; i++)
                #pragma unroll
                for (int j = 0; j < 4; j++)
                    o[i][j] = fmaf(pv[i], vv[j], o[i][j]);
        }
        __syncthreads();
    }

    // Normalize and write O in [b, s, h*HD] layout
    float* Og = g_o + (size_t)(b*SQ + q0)*DM + h*HD;
    #pragma unroll
    for (int i = 0; i < 4; i++) {
        int q = oy + 16*i;
        float inv = 1.f / lrow[q];
        #pragma unroll
        for (int j = 0; j < 4; j++)
            Og[(size_t)q*DM + ox*4 + j] = o[i][j] * inv;
    }
}

extern "C" void kernel_launch(void* const* d_in, const int* in_sizes, int n_in,
                              void* d_out, int out_size)
{
    const float* x  = (const float*)d_in[0];
    const float* wq = (const float*)d_in[1];
    const float* bq = (const float*)d_in[2];
    const float* wk = (const float*)d_in[3];
    const float* bk = (const float*)d_in[4];
    const float* wv = (const float*)d_in[5];
    const float* bv = (const float*)d_in[6];
    const float* wo = (const float*)d_in[7];
    const float* bo = (const float*)d_in[8];
    float* out = (float*)d_out;

    float *q, *k, *v, *o;
    cudaGetSymbolAddress((void**)&q, g_q);
    cudaGetSymbolAddress((void**)&k, g_k);
    cudaGetSymbolAddress((void**)&v, g_v);
    cudaGetSymbolAddress((void**)&o, g_o);

    dim3 gg(DM/64, MR/64);   // (16, 64)
    gemm_kernel<<<gg, 256>>>(x, wq, bq, q, MR, DM, DM);
    gemm_kernel<<<gg, 256>>>(x, wk, bk, k, MR, DM, DM);
    gemm_kernel<<<gg, 256>>>(x, wv, bv, v, MR, DM, DM);

    attn_kernel<<<dim3(SQ/64, HH, BZ), 256>>>();

    gemm_kernel<<<gg, 256>>>(o, wo, bo, out, MR, DM, DM);
}

// round 5
// speedup vs baseline: 1.0490x; 1.0490x over previous
#include <cuda_runtime.h>
#include <cuda_bf16.h>
#include <cstdint>
#include <math.h>

#define BZ   2
#define SQ   2048
#define DM   1024
#define HH   16
#define HD   64
#define MR   (BZ*SQ)      // 4096 rows
#define K3   (3*DM)       // 3072 expanded-K

// ---- device-global scratch (no allocations allowed) ----
__device__ float g_q[(size_t)MR*DM];
__device__ float g_k[(size_t)MR*DM];
__device__ float g_v[(size_t)MR*DM];
__device__ float g_o[(size_t)MR*DM];
__device__ __nv_bfloat16 g_x3[(size_t)MR*K3];
__device__ __nv_bfloat16 g_o3[(size_t)MR*K3];
__device__ __nv_bfloat16 g_wq3[(size_t)K3*DM];
__device__ __nv_bfloat16 g_wk3[(size_t)K3*DM];
__device__ __nv_bfloat16 g_wv3[(size_t)K3*DM];
__device__ __nv_bfloat16 g_wo3[(size_t)K3*DM];

// ---------------------------------------------------------------------------
// Split-expansion kernels: hi = bf16(x), lo = bf16(x - hi)
// A3[m, 0:K]=hi, A3[m, K:2K]=hi, A3[m, 2K:3K]=lo
// B3[0:K, n]=hi, B3[K:2K, n]=lo, B3[2K:3K, n]=hi
// so A3 @ B3 (over 3K) = Ah*Bh + Ah*Bl + Al*Bh.
// ---------------------------------------------------------------------------
__global__ __launch_bounds__(256) void expand_a3(
    const float* __restrict__ src, __nv_bfloat16* __restrict__ dst, int M, int K)
{
    int idx = blockIdx.x*256 + threadIdx.x;
    if (idx >= M*K) return;
    int m = idx / K, k = idx - m*K;
    float x = src[idx];
    __nv_bfloat16 h = __float2bfloat16(x);
    __nv_bfloat16 l = __float2bfloat16(x - __bfloat162float(h));
    size_t base = (size_t)m*3*K;
    dst[base + k] = h;
    dst[base + K + k] = h;
    dst[base + 2*K + k] = l;
}

__global__ __launch_bounds__(256) void expand_b3(
    const float* __restrict__ src, __nv_bfloat16* __restrict__ dst, int K, int N)
{
    int idx = blockIdx.x*256 + threadIdx.x;
    if (idx >= K*N) return;
    int k = idx / N, n = idx - k*N;
    float x = src[idx];
    __nv_bfloat16 h = __float2bfloat16(x);
    __nv_bfloat16 l = __float2bfloat16(x - __bfloat162float(h));
    dst[(size_t)k*N + n]         = h;
    dst[(size_t)(K+k)*N + n]     = l;
    dst[(size_t)(2*K+k)*N + n]   = h;
}

// ---------------------------------------------------------------------------
// bf16 tensor-core GEMM: C[M,N] = A3[M,K3] @ B3[K3,N] + bias
// Block tile 128x128, 256 threads (8 warps as 2x4), warp tile 64x32,
// mma.sync m16n8k16. Smem padded stride 36 bf16 (18 u32) -> conflict-free
// fragment loads.
// ---------------------------------------------------------------------------
__global__ __launch_bounds__(256) void gemm_bf16(
    const __nv_bfloat16* __restrict__ A, const __nv_bfloat16* __restrict__ B,
    const float* __restrict__ bias, float* __restrict__ C,
    int M, int N, int Kx)
{
    __shared__ uint32_t As[128*18];   // [row][k-u32], 32 bf16 per row + pad
    __shared__ uint32_t Bs[128*18];   // [n][k-u32] (transposed), + pad

    int tid = threadIdx.x;
    int lane = tid & 31;
    int w = tid >> 5;
    int wm = w >> 2;          // 0..1  -> m offset 64*wm
    int wn = w & 3;           // 0..3  -> n offset 32*wn
    int g = lane >> 2;        // group 0..7
    int t = lane & 3;

    int m0 = blockIdx.y * 128;
    int n0 = blockIdx.x * 128;

    float acc[4][4][4];
    #pragma unroll
    for (int i = 0; i < 4; i++)
        #pragma unroll
        for (int j = 0; j < 4; j++)
            #pragma unroll
            for (int r = 0; r < 4; r++) acc[i][j][r] = 0.f;

    __nv_bfloat16* Bsh = (__nv_bfloat16*)Bs;

    for (int k0 = 0; k0 < Kx; k0 += 32) {
        // A tile: 128 rows x 16 u32
        #pragma unroll
        for (int i = 0; i < 8; i++) {
            int u = tid + i*256;
            int r = u >> 4, c = u & 15;
            const uint32_t* ga = (const uint32_t*)(A + (size_t)(m0+r)*Kx + k0);
            As[r*18 + c] = ga[c];
        }
        // B tile: 32 k-rows x 128 n, transposed into Bs[n][k]
        #pragma unroll
        for (int i = 0; i < 8; i++) {
            int u = tid + i*256;
            int k = u >> 6, nc = u & 63;
            const uint32_t* gb = (const uint32_t*)(B + (size_t)(k0+k)*N + n0);
            uint32_t val = gb[nc];
            Bsh[(2*nc)*36 + k]   = ((__nv_bfloat16*)&val)[0];
            Bsh[(2*nc+1)*36 + k] = ((__nv_bfloat16*)&val)[1];
        }
        __syncthreads();

        #pragma unroll
        for (int s = 0; s < 2; s++) {
            uint32_t a[4][4], b[4][2];
            #pragma unroll
            for (int mt = 0; mt < 4; mt++) {
                int ar = (wm*64 + mt*16 + g)*18 + s*8 + t;
                a[mt][0] = As[ar];
                a[mt][1] = As[ar + 8*18];
                a[mt][2] = As[ar + 4];
                a[mt][3] = As[ar + 8*18 + 4];
            }
            #pragma unroll
            for (int nt = 0; nt < 4; nt++) {
                int br = (wn*32 + nt*8 + g)*18 + s*8 + t;
                b[nt][0] = Bs[br];
                b[nt][1] = Bs[br + 4];
            }
            #pragma unroll
            for (int mt = 0; mt < 4; mt++)
                #pragma unroll
                for (int nt = 0; nt < 4; nt++) {
                    asm volatile(
                        "mma.sync.aligned.m16n8k16.row.col.f32.bf16.bf16.f32 "
                        "{%0,%1,%2,%3}, {%4,%5,%6,%7}, {%8,%9}, {%0,%1,%2,%3};"
                        : "+f"(acc[mt][nt][0]), "+f"(acc[mt][nt][1]),
                          "+f"(acc[mt][nt][2]), "+f"(acc[mt][nt][3])
                        : "r"(a[mt][0]), "r"(a[mt][1]), "r"(a[mt][2]), "r"(a[mt][3]),
                          "r"(b[nt][0]), "r"(b[nt][1]));
                }
        }
        __syncthreads();
    }

    // Epilogue: add bias, write fp32
    #pragma unroll
    for (int mt = 0; mt < 4; mt++) {
        int row0 = m0 + wm*64 + mt*16 + g;
        #pragma unroll
        for (int nt = 0; nt < 4; nt++) {
            int col = n0 + wn*32 + nt*8 + 2*t;
            float b0 = bias[col], b1 = bias[col+1];
            C[(size_t)row0*N + col]     = acc[mt][nt][0] + b0;
            C[(size_t)row0*N + col + 1] = acc[mt][nt][1] + b1;
            C[(size_t)(row0+8)*N + col]     = acc[mt][nt][2] + b0;
            C[(size_t)(row0+8)*N + col + 1] = acc[mt][nt][3] + b1;
        }
    }
}

// ---------------------------------------------------------------------------
// Flash attention (fp32 SIMT): one block per (64 q-rows, head, batch),
// k-tiles of 32, static smem < 48KB.
// ---------------------------------------------------------------------------
#define PST 68
#define PSS 36

__global__ __launch_bounds__(256) void attn_kernel()
{
    __shared__ float Qs[64*PST];
    __shared__ float Ks[32*PST];
    __shared__ float Vs[32*PST];
    __shared__ float Ps[64*PSS];
    __shared__ float mrow[64], lrow[64], arow[64];

    int tid = threadIdx.x;
    int q0 = blockIdx.x * 64;
    int h  = blockIdx.y;
    int b  = blockIdx.z;
    const float scale = 0.125f;

    int sx = tid & 7;
    int sy = tid >> 3;
    int ox = tid & 15;
    int oy = tid >> 4;

    const float* Qg = g_q + (size_t)(b*SQ + q0)*DM + h*HD;
    #pragma unroll
    for (int i = 0; i < 4; i++) {
        int idx4 = tid + i*256;
        int r = idx4 >> 4, c4 = idx4 & 15;
        float4 v = *(const float4*)(Qg + (size_t)r*DM + c4*4);
        v.x *= scale; v.y *= scale; v.z *= scale; v.w *= scale;
        *(float4*)&Qs[r*PST + c4*4] = v;
    }
    if (tid < 64) { mrow[tid] = -INFINITY; lrow[tid] = 0.f; }

    float o[4][4] = {};
    __syncthreads();

    for (int k0 = 0; k0 < SQ; k0 += 32) {
        const float* Kg = g_k + (size_t)(b*SQ + k0)*DM + h*HD;
        const float* Vg = g_v + (size_t)(b*SQ + k0)*DM + h*HD;
        #pragma unroll
        for (int i = 0; i < 2; i++) {
            int idx4 = tid + i*256;
            int r = idx4 >> 4, c4 = idx4 & 15;
            *(float4*)&Ks[r*PST + c4*4] = *(const float4*)(Kg + (size_t)r*DM + c4*4);
            *(float4*)&Vs[r*PST + c4*4] = *(const float4*)(Vg + (size_t)r*DM + c4*4);
        }
        __syncthreads();

        float s[2][4] = {};
        #pragma unroll 16
        for (int d = 0; d < 64; d++) {
            float qv[2], kv[4];
            qv[0] = Qs[sy*PST + d];
            qv[1] = Qs[(sy+32)*PST + d];
            #pragma unroll
            for (int j = 0; j < 4; j++) kv[j] = Ks[(sx*4+j)*PST + d];
            #pragma unroll
            for (int i = 0; i < 2; i++)
                #pragma unroll
                for (int j = 0; j < 4; j++)
                    s[i][j] = fmaf(qv[i], kv[j], s[i][j]);
        }
        #pragma unroll
        for (int i = 0; i < 2; i++) {
            int q = sy + 32*i;
            *(float4*)&Ps[q*PSS + sx*4] = make_float4(s[i][0], s[i][1], s[i][2], s[i][3]);
        }
        __syncthreads();

        if (tid < 64) {
            int q = tid;
            float mo = mrow[q];
            float mx = mo;
            #pragma unroll 8
            for (int j = 0; j < 32; j++) mx = fmaxf(mx, Ps[q*PSS + j]);
            float sum = 0.f;
            #pragma unroll 8
            for (int j = 0; j < 32; j++) {
                float p = __expf(Ps[q*PSS + j] - mx);
                Ps[q*PSS + j] = p;
                sum += p;
            }
            float al = __expf(mo - mx);
            lrow[q] = lrow[q]*al + sum;
            mrow[q] = mx;
            arow[q] = al;
        }
        __syncthreads();

        float al[4];
        #pragma unroll
        for (int i = 0; i < 4; i++) al[i] = arow[oy + 16*i];
        #pragma unroll
        for (int i = 0; i < 4; i++)
            #pragma unroll
            for (int j = 0; j < 4; j++)
                o[i][j] *= al[i];

        #pragma unroll 8
        for (int kk = 0; kk < 32; kk++) {
            float pv[4], vv[4];
            #pragma unroll
            for (int i = 0; i < 4; i++) pv[i] = Ps[(oy + 16*i)*PSS + kk];
            #pragma unroll
            for (int j = 0; j < 4; j++) vv[j] = Vs[kk*PST + ox*4 + j];
            #pragma unroll
            for (int i = 0; i < 4; i++)
                #pragma unroll
                for (int j = 0; j < 4; j++)
                    o[i][j] = fmaf(pv[i], vv[j], o[i][j]);
        }
        __syncthreads();
    }

    float* Og = g_o + (size_t)(b*SQ + q0)*DM + h*HD;
    #pragma unroll
    for (int i = 0; i < 4; i++) {
        int q = oy + 16*i;
        float inv = 1.f / lrow[q];
        #pragma unroll
        for (int j = 0; j < 4; j++)
            Og[(size_t)q*DM + ox*4 + j] = o[i][j] * inv;
    }
}

extern "C" void kernel_launch(void* const* d_in, const int* in_sizes, int n_in,
                              void* d_out, int out_size)
{
    const float* x  = (const float*)d_in[0];
    const float* wq = (const float*)d_in[1];
    const float* bq = (const float*)d_in[2];
    const float* wk = (const float*)d_in[3];
    const float* bk = (const float*)d_in[4];
    const float* wv = (const float*)d_in[5];
    const float* bv = (const float*)d_in[6];
    const float* wo = (const float*)d_in[7];
    const float* bo = (const float*)d_in[8];
    float* out = (float*)d_out;

    float *q, *k, *v, *o;
    __nv_bfloat16 *x3, *o3, *wq3, *wk3, *wv3, *wo3;
    cudaGetSymbolAddress((void**)&q, g_q);
    cudaGetSymbolAddress((void**)&k, g_k);
    cudaGetSymbolAddress((void**)&v, g_v);
    cudaGetSymbolAddress((void**)&o, g_o);
    cudaGetSymbolAddress((void**)&x3, g_x3);
    cudaGetSymbolAddress((void**)&o3, g_o3);
    cudaGetSymbolAddress((void**)&wq3, g_wq3);
    cudaGetSymbolAddress((void**)&wk3, g_wk3);
    cudaGetSymbolAddress((void**)&wv3, g_wv3);
    cudaGetSymbolAddress((void**)&wo3, g_wo3);

    int eb = (MR*DM + 255)/256;     // elems for activations
    int wb = (DM*DM + 255)/256;     // elems for weights

    expand_a3<<<eb, 256>>>(x, x3, MR, DM);
    expand_b3<<<wb, 256>>>(wq, wq3, DM, DM);
    expand_b3<<<wb, 256>>>(wk, wk3, DM, DM);
    expand_b3<<<wb, 256>>>(wv, wv3, DM, DM);
    expand_b3<<<wb, 256>>>(wo, wo3, DM, DM);

    dim3 gg(DM/128, MR/128);        // (8, 32)
    gemm_bf16<<<gg, 256>>>(x3, wq3, bq, q, MR, DM, K3);
    gemm_bf16<<<gg, 256>>>(x3, wk3, bk, k, MR, DM, K3);
    gemm_bf16<<<gg, 256>>>(x3, wv3, bv, v, MR, DM, K3);

    attn_kernel<<<dim3(SQ/64, HH, BZ), 256>>>();

    expand_a3<<<eb, 256>>>(o, o3, MR, DM);
    gemm_bf16<<<gg, 256>>>(o3, wo3, bo, out, MR, DM, K3);
}